// round 1
// baseline (speedup 1.0000x reference)
#include <cuda_runtime.h>
#include <math.h>

#define NU 40000
#define NI 20000
#define NT 60000
#define DD 256
#define NNZ_ADJ 960000
#define NNZ_UP  640000
#define NNZ_IP  320000

// ---------------- scratch (device globals: allocation-guard safe) ----------
__device__ float g_agg[(size_t)NT * DD];   // spmm(adj, pre0)
__device__ float g_pair[(size_t)NT * DD];  // rows [0,NU): spmm_up ; rows [NU,NT): spmm_ip
__device__ float g_emb[(size_t)NT * DD];   // tanh(agg @ Q_sel)
__device__ float g_h[(size_t)NT * DD];     // tanh(pre0@Wtop + emb@Wbot + b)
__device__ float g_norm[NT];               // row sum-of-squares of g_h

// ---------------- zero-init ------------------------------------------------
__global__ void k_zero() {
    size_t i = (size_t)blockIdx.x * blockDim.x + threadIdx.x;
    size_t stride = (size_t)gridDim.x * blockDim.x;
    const size_t n4 = (size_t)NT * DD / 4;
    float4 z = make_float4(0.f, 0.f, 0.f, 0.f);
    for (size_t j = i; j < n4; j += stride) {
        reinterpret_cast<float4*>(g_agg)[j]  = z;
        reinterpret_cast<float4*>(g_pair)[j] = z;
    }
    for (size_t j = i; j < (size_t)NT; j += stride) g_norm[j] = 0.f;
}

// ---------------- SpMM (warp per edge, atomic scatter) ---------------------
__global__ void k_spmm_adj(const int* __restrict__ rows, const int* __restrict__ cols,
                           const float* __restrict__ vals,
                           const float* __restrict__ Ue, const float* __restrict__ Ie) {
    int e = (blockIdx.x * blockDim.x + threadIdx.x) >> 5;
    if (e >= NNZ_ADJ) return;
    int lane = threadIdx.x & 31;
    int r = rows[e];
    int c = cols[e];
    float v = vals[e];
    const float* x = (c < NU) ? (Ue + (size_t)c * DD) : (Ie + (size_t)(c - NU) * DD);
    x += lane * 8;
    float* y = g_agg + (size_t)r * DD + lane * 8;
    float4 a = *reinterpret_cast<const float4*>(x);
    float4 b = *reinterpret_cast<const float4*>(x + 4);
    atomicAdd(y + 0, a.x * v); atomicAdd(y + 1, a.y * v);
    atomicAdd(y + 2, a.z * v); atomicAdd(y + 3, a.w * v);
    atomicAdd(y + 4, b.x * v); atomicAdd(y + 5, b.y * v);
    atomicAdd(y + 6, b.z * v); atomicAdd(y + 7, b.w * v);
}

__global__ void k_spmm_pair(const int* __restrict__ rows, const int* __restrict__ cols,
                            const float* __restrict__ vals, int nnz,
                            const float* __restrict__ X, int row_off) {
    int e = (blockIdx.x * blockDim.x + threadIdx.x) >> 5;
    if (e >= nnz) return;
    int lane = threadIdx.x & 31;
    int r = rows[e];
    int c = cols[e];
    float v = vals[e];
    const float* x = X + (size_t)c * DD + lane * 8;
    float* y = g_pair + (size_t)(row_off + r) * DD + lane * 8;
    float4 a = *reinterpret_cast<const float4*>(x);
    float4 b = *reinterpret_cast<const float4*>(x + 4);
    atomicAdd(y + 0, a.x * v); atomicAdd(y + 1, a.y * v);
    atomicAdd(y + 2, a.z * v); atomicAdd(y + 3, a.w * v);
    atomicAdd(y + 4, b.x * v); atomicAdd(y + 5, b.y * v);
    atomicAdd(y + 6, b.z * v); atomicAdd(y + 7, b.w * v);
}

// ---------------- fp32 SIMT GEMM core (64x64 tile, 256 thr, 4x4 micro) -----
#define BM 64
#define BN 64
#define BK 16
#define TPB 256

// acc += A[row0:row0+64, :256] @ B[:, col0:col0+64]
// A row r comes from A1 (r < split) or A2 (r - split); out-of-range rows -> 0.
__device__ __forceinline__ void gemm_accum(
    float acc[4][4],
    float As[BK][BM + 4], float Bs[BK][BN],
    const float* __restrict__ A1, const float* __restrict__ A2, int split,
    const float* __restrict__ B, int row0, int col0)
{
    const int tid = threadIdx.x;
    const int tx = tid & 15, ty = tid >> 4;
    const int ar = tid >> 2;            // 0..63
    const int ak = (tid & 3) << 2;      // 0,4,8,12
    const int br = tid >> 4;            // 0..15
    const int bc = (tid & 15) << 2;     // 0..60

    const int grow = row0 + ar;
    const float* arow = nullptr;
    if (grow < NT)
        arow = (grow < split) ? (A1 + (size_t)grow * DD)
                              : (A2 + (size_t)(grow - split) * DD);

    for (int k0 = 0; k0 < DD; k0 += BK) {
        float4 av = make_float4(0.f, 0.f, 0.f, 0.f);
        if (arow) av = *reinterpret_cast<const float4*>(arow + k0 + ak);
        As[ak + 0][ar] = av.x;
        As[ak + 1][ar] = av.y;
        As[ak + 2][ar] = av.z;
        As[ak + 3][ar] = av.w;
        *reinterpret_cast<float4*>(&Bs[br][bc]) =
            *reinterpret_cast<const float4*>(B + (size_t)(k0 + br) * DD + col0 + bc);
        __syncthreads();
#pragma unroll
        for (int kk = 0; kk < BK; kk++) {
            float4 a = *reinterpret_cast<const float4*>(&As[kk][ty << 2]);
            float4 b = *reinterpret_cast<const float4*>(&Bs[kk][tx << 2]);
            acc[0][0] += a.x * b.x; acc[0][1] += a.x * b.y; acc[0][2] += a.x * b.z; acc[0][3] += a.x * b.w;
            acc[1][0] += a.y * b.x; acc[1][1] += a.y * b.y; acc[1][2] += a.y * b.z; acc[1][3] += a.y * b.w;
            acc[2][0] += a.z * b.x; acc[2][1] += a.z * b.y; acc[2][2] += a.z * b.z; acc[2][3] += a.z * b.w;
            acc[3][0] += a.w * b.x; acc[3][1] += a.w * b.y; acc[3][2] += a.w * b.z; acc[3][3] += a.w * b.w;
        }
        __syncthreads();
    }
}

// ---------------- K1: emb = tanh(agg @ Q_sel) -------------------------------
__global__ __launch_bounds__(TPB) void k_emb(const float* __restrict__ Qu,
                                             const float* __restrict__ Qi) {
    __shared__ float As[BK][BM + 4];
    __shared__ float Bs[BK][BN];
    const int row0 = blockIdx.x * BM;
    const int col0 = blockIdx.y * BN;
    const float* B = (row0 < NU) ? Qu : Qi;   // tiles never straddle row 40000 (40000 % 64 == 0)
    float acc[4][4] = {};
    gemm_accum(acc, As, Bs, g_agg, g_agg, NT, B, row0, col0);

    const int tx = threadIdx.x & 15, ty = threadIdx.x >> 4;
#pragma unroll
    for (int i = 0; i < 4; i++) {
        int row = row0 + (ty << 2) + i;
        if (row >= NT) break;
        float4 o;
        o.x = tanhf(acc[i][0]); o.y = tanhf(acc[i][1]);
        o.z = tanhf(acc[i][2]); o.w = tanhf(acc[i][3]);
        *reinterpret_cast<float4*>(g_emb + (size_t)row * DD + col0 + (tx << 2)) = o;
    }
}

// ---------------- K2: h = tanh(pre0@Wtop + emb@Wbot + b); accumulate sumsq --
__global__ __launch_bounds__(TPB) void k_hidden(
    const float* __restrict__ Ue, const float* __restrict__ Ie,
    const float* __restrict__ Wu, const float* __restrict__ Wi,
    const float* __restrict__ bu, const float* __restrict__ bi) {
    __shared__ float As[BK][BM + 4];
    __shared__ float Bs[BK][BN];
    const int row0 = blockIdx.x * BM;
    const int col0 = blockIdx.y * BN;
    const bool user = (row0 < NU);
    const float* W = user ? Wu : Wi;          // [512,256] row-major
    const float* bias = user ? bu : bi;
    float acc[4][4] = {};
    gemm_accum(acc, As, Bs, Ue, Ie, NU, W, row0, col0);                      // pre0 @ W_top
    gemm_accum(acc, As, Bs, g_emb, g_emb, NT, W + (size_t)DD * DD, row0, col0); // emb @ W_bot

    const int tx = threadIdx.x & 15, ty = threadIdx.x >> 4;
    float bv[4];
#pragma unroll
    for (int j = 0; j < 4; j++) bv[j] = bias[col0 + (tx << 2) + j];

#pragma unroll
    for (int i = 0; i < 4; i++) {
        int row = row0 + (ty << 2) + i;
        if (row >= NT) break;
        float4 o;
        o.x = tanhf(acc[i][0] + bv[0]);
        o.y = tanhf(acc[i][1] + bv[1]);
        o.z = tanhf(acc[i][2] + bv[2]);
        o.w = tanhf(acc[i][3] + bv[3]);
        *reinterpret_cast<float4*>(g_h + (size_t)row * DD + col0 + (tx << 2)) = o;
        float ss = o.x * o.x + o.y * o.y + o.z * o.z + o.w * o.w;
        atomicAdd(&g_norm[row], ss);
    }
}

// ---------------- K3: out = h/max(||h||,1e-12) + tanh(pair @ M_sel) ---------
__global__ __launch_bounds__(TPB) void k_out(const float* __restrict__ Mu,
                                             const float* __restrict__ Mi,
                                             float* __restrict__ Out) {
    __shared__ float As[BK][BM + 4];
    __shared__ float Bs[BK][BN];
    const int row0 = blockIdx.x * BM;
    const int col0 = blockIdx.y * BN;
    const float* M = (row0 < NU) ? Mu : Mi;
    float acc[4][4] = {};
    gemm_accum(acc, As, Bs, g_pair, g_pair, NT, M, row0, col0);

    const int tx = threadIdx.x & 15, ty = threadIdx.x >> 4;
#pragma unroll
    for (int i = 0; i < 4; i++) {
        int row = row0 + (ty << 2) + i;
        if (row >= NT) break;
        float nrm = sqrtf(g_norm[row]);
        float s = 1.f / fmaxf(nrm, 1e-12f);
        float4 h = *reinterpret_cast<const float4*>(g_h + (size_t)row * DD + col0 + (tx << 2));
        float4 o;
        o.x = h.x * s + tanhf(acc[i][0]);
        o.y = h.y * s + tanhf(acc[i][1]);
        o.z = h.z * s + tanhf(acc[i][2]);
        o.w = h.w * s + tanhf(acc[i][3]);
        *reinterpret_cast<float4*>(Out + (size_t)row * DD + col0 + (tx << 2)) = o;
    }
}

// ---------------- host launch -----------------------------------------------
extern "C" void kernel_launch(void* const* d_in, const int* in_sizes, int n_in,
                              void* d_out, int out_size) {
    const int*   adj_rows = (const int*)d_in[0];
    const int*   adj_cols = (const int*)d_in[1];
    const float* adj_vals = (const float*)d_in[2];
    const int*   up_rows  = (const int*)d_in[3];
    const int*   up_cols  = (const int*)d_in[4];
    const float* up_vals  = (const float*)d_in[5];
    const int*   ip_rows  = (const int*)d_in[6];
    const int*   ip_cols  = (const int*)d_in[7];
    const float* ip_vals  = (const float*)d_in[8];
    const float* Ue       = (const float*)d_in[9];
    const float* Ie       = (const float*)d_in[10];
    const float* Qu       = (const float*)d_in[11];
    const float* Wu       = (const float*)d_in[12];
    const float* bu       = (const float*)d_in[13];
    const float* Qi       = (const float*)d_in[14];
    const float* Wi       = (const float*)d_in[15];
    const float* bi       = (const float*)d_in[16];
    const float* Mu       = (const float*)d_in[17];
    const float* Mi       = (const float*)d_in[18];
    float* out = (float*)d_out;

    k_zero<<<4096, 256>>>();

    k_spmm_adj<<<(NNZ_ADJ * 32 + 255) / 256, 256>>>(adj_rows, adj_cols, adj_vals, Ue, Ie);
    k_spmm_pair<<<(NNZ_UP * 32 + 255) / 256, 256>>>(up_rows, up_cols, up_vals, NNZ_UP, Ue, 0);
    k_spmm_pair<<<(NNZ_IP * 32 + 255) / 256, 256>>>(ip_rows, ip_cols, ip_vals, NNZ_IP, Ie, NU);

    dim3 grid((NT + BM - 1) / BM, DD / BN);
    k_emb<<<grid, TPB>>>(Qu, Qi);
    k_hidden<<<grid, TPB>>>(Ue, Ie, Wu, Wi, bu, bi);
    k_out<<<grid, TPB>>>(Mu, Mi, out);
}

// round 2
// speedup vs baseline: 2.7007x; 2.7007x over previous
#include <cuda_runtime.h>
#include <math.h>

#define NU 40000
#define NI 20000
#define NT 60000
#define DD 256
#define NNZ_ADJ 960000
#define NNZ_UP  640000
#define NNZ_IP  320000

// ---------------- scratch (device globals: allocation-guard safe) ----------
__device__ float g_agg[(size_t)NT * DD];   // spmm(adj, pre0)
__device__ float g_pair[(size_t)NT * DD];  // rows [0,NU): spmm_up ; [NU,NT): spmm_ip
__device__ float g_emb[(size_t)NT * DD];   // tanh(agg @ Q_sel)
__device__ float g_h[(size_t)NT * DD];     // tanh(pre0@Wtop + emb@Wbot + b)
__device__ float g_norm[NT];               // row sum-of-squares of g_h

// CSR build scratch (reused sequentially for adj / up / ip)
__device__ int   g_cnt[NT];
__device__ int   g_rs[NT + 1];
__device__ int   g_cur[NT];
__device__ int   g_ccol[NNZ_ADJ];
__device__ float g_cval[NNZ_ADJ];

// ---------------- tiny init kernels ----------------------------------------
__global__ void k_zero_norm() {
    int i = blockIdx.x * blockDim.x + threadIdx.x;
    if (i < NT) g_norm[i] = 0.f;
}
__global__ void k_zero_cnt(int n) {
    int i = blockIdx.x * blockDim.x + threadIdx.x;
    if (i < n) g_cnt[i] = 0;
}
__global__ void k_hist(const int* __restrict__ rows, int nnz) {
    int i = blockIdx.x * blockDim.x + threadIdx.x;
    if (i < nnz) atomicAdd(&g_cnt[rows[i]], 1);
}
// exclusive scan g_cnt[0..n) -> g_rs[0..n], one block of 1024 threads
__global__ void k_scan(int n) {
    __shared__ int s[1024];
    int tid = threadIdx.x;
    int per = (n + 1023) / 1024;
    int beg = tid * per;
    int end = min(beg + per, n);
    int sum = 0;
    for (int i = beg; i < end; i++) sum += g_cnt[i];
    s[tid] = sum;
    __syncthreads();
    for (int off = 1; off < 1024; off <<= 1) {
        int v = (tid >= off) ? s[tid - off] : 0;
        __syncthreads();
        s[tid] += v;
        __syncthreads();
    }
    int run = (tid == 0) ? 0 : s[tid - 1];
    for (int i = beg; i < end; i++) { g_rs[i] = run; run += g_cnt[i]; }
    if (end == n) g_rs[n] = run;   // threads covering (or past) the tail hold the total
}
__global__ void k_copy_cur(int n) {
    int i = blockIdx.x * blockDim.x + threadIdx.x;
    if (i < n) g_cur[i] = g_rs[i];
}
__global__ void k_scatter(const int* __restrict__ rows, const int* __restrict__ cols,
                          const float* __restrict__ vals, int nnz) {
    int i = blockIdx.x * blockDim.x + threadIdx.x;
    if (i >= nnz) return;
    int p = atomicAdd(&g_cur[rows[i]], 1);
    g_ccol[p] = cols[i];
    g_cval[p] = vals[i];
}

// ---------------- atomic-free CSR SpMM (warp per row) ----------------------
// Y[r,:] = sum_e v_e * X(col_e)[:], cols from {X1 if c<colsplit else X2[c-colsplit]}
__global__ __launch_bounds__(256) void k_spmm_csr(
    const float* __restrict__ X1, const float* __restrict__ X2, int colsplit,
    float* __restrict__ Y, int n_rows)
{
    int r = blockIdx.x * 8 + (threadIdx.x >> 5);
    if (r >= n_rows) return;
    int lane = threadIdx.x & 31;
    float4 a0 = make_float4(0.f, 0.f, 0.f, 0.f);
    float4 a1 = a0;
    int beg = g_rs[r], end = g_rs[r + 1];
    for (int e = beg; e < end; e++) {
        int c = g_ccol[e];
        float v = g_cval[e];
        const float* x = (c < colsplit) ? (X1 + (size_t)c * DD)
                                        : (X2 + (size_t)(c - colsplit) * DD);
        float4 b0 = *reinterpret_cast<const float4*>(x + lane * 4);
        float4 b1 = *reinterpret_cast<const float4*>(x + 128 + lane * 4);
        a0.x += v * b0.x; a0.y += v * b0.y; a0.z += v * b0.z; a0.w += v * b0.w;
        a1.x += v * b1.x; a1.y += v * b1.y; a1.z += v * b1.z; a1.w += v * b1.w;
    }
    float* y = Y + (size_t)r * DD;
    *reinterpret_cast<float4*>(y + lane * 4) = a0;
    *reinterpret_cast<float4*>(y + 128 + lane * 4) = a1;
}

// ---------------- fp32 SIMT GEMM core (64x64 tile, 256 thr, 4x4 micro) -----
#define BM 64
#define BN 64
#define BK 16
#define TPB 256

__device__ __forceinline__ void gemm_accum(
    float acc[4][4],
    float As[BK][BM + 4], float Bs[BK][BN],
    const float* __restrict__ A1, const float* __restrict__ A2, int split,
    const float* __restrict__ B, int row0, int col0)
{
    const int tid = threadIdx.x;
    const int tx = tid & 15, ty = tid >> 4;
    const int ar = tid >> 2;
    const int ak = (tid & 3) << 2;
    const int br = tid >> 4;
    const int bc = (tid & 15) << 2;

    const int grow = row0 + ar;
    const float* arow = nullptr;
    if (grow < NT)
        arow = (grow < split) ? (A1 + (size_t)grow * DD)
                              : (A2 + (size_t)(grow - split) * DD);

    for (int k0 = 0; k0 < DD; k0 += BK) {
        float4 av = make_float4(0.f, 0.f, 0.f, 0.f);
        if (arow) av = *reinterpret_cast<const float4*>(arow + k0 + ak);
        As[ak + 0][ar] = av.x;
        As[ak + 1][ar] = av.y;
        As[ak + 2][ar] = av.z;
        As[ak + 3][ar] = av.w;
        *reinterpret_cast<float4*>(&Bs[br][bc]) =
            *reinterpret_cast<const float4*>(B + (size_t)(k0 + br) * DD + col0 + bc);
        __syncthreads();
#pragma unroll
        for (int kk = 0; kk < BK; kk++) {
            float4 a = *reinterpret_cast<const float4*>(&As[kk][ty << 2]);
            float4 b = *reinterpret_cast<const float4*>(&Bs[kk][tx << 2]);
            acc[0][0] += a.x * b.x; acc[0][1] += a.x * b.y; acc[0][2] += a.x * b.z; acc[0][3] += a.x * b.w;
            acc[1][0] += a.y * b.x; acc[1][1] += a.y * b.y; acc[1][2] += a.y * b.z; acc[1][3] += a.y * b.w;
            acc[2][0] += a.z * b.x; acc[2][1] += a.z * b.y; acc[2][2] += a.z * b.z; acc[2][3] += a.z * b.w;
            acc[3][0] += a.w * b.x; acc[3][1] += a.w * b.y; acc[3][2] += a.w * b.z; acc[3][3] += a.w * b.w;
        }
        __syncthreads();
    }
}

// ---------------- K1: emb = tanh(agg @ Q_sel) -------------------------------
__global__ __launch_bounds__(TPB) void k_emb(const float* __restrict__ Qu,
                                             const float* __restrict__ Qi) {
    __shared__ float As[BK][BM + 4];
    __shared__ float Bs[BK][BN];
    const int row0 = blockIdx.x * BM;
    const int col0 = blockIdx.y * BN;
    const float* B = (row0 < NU) ? Qu : Qi;   // 40000 % 64 == 0: tiles never straddle
    float acc[4][4] = {};
    gemm_accum(acc, As, Bs, g_agg, g_agg, NT, B, row0, col0);

    const int tx = threadIdx.x & 15, ty = threadIdx.x >> 4;
#pragma unroll
    for (int i = 0; i < 4; i++) {
        int row = row0 + (ty << 2) + i;
        if (row >= NT) break;
        float4 o;
        o.x = tanhf(acc[i][0]); o.y = tanhf(acc[i][1]);
        o.z = tanhf(acc[i][2]); o.w = tanhf(acc[i][3]);
        *reinterpret_cast<float4*>(g_emb + (size_t)row * DD + col0 + (tx << 2)) = o;
    }
}

// ---------------- K2: h = tanh(pre0@Wtop + emb@Wbot + b); accumulate sumsq --
__global__ __launch_bounds__(TPB) void k_hidden(
    const float* __restrict__ Ue, const float* __restrict__ Ie,
    const float* __restrict__ Wu, const float* __restrict__ Wi,
    const float* __restrict__ bu, const float* __restrict__ bi) {
    __shared__ float As[BK][BM + 4];
    __shared__ float Bs[BK][BN];
    const int row0 = blockIdx.x * BM;
    const int col0 = blockIdx.y * BN;
    const bool user = (row0 < NU);
    const float* W = user ? Wu : Wi;
    const float* bias = user ? bu : bi;
    float acc[4][4] = {};
    gemm_accum(acc, As, Bs, Ue, Ie, NU, W, row0, col0);
    gemm_accum(acc, As, Bs, g_emb, g_emb, NT, W + (size_t)DD * DD, row0, col0);

    const int tx = threadIdx.x & 15, ty = threadIdx.x >> 4;
    float bv[4];
#pragma unroll
    for (int j = 0; j < 4; j++) bv[j] = bias[col0 + (tx << 2) + j];

#pragma unroll
    for (int i = 0; i < 4; i++) {
        int row = row0 + (ty << 2) + i;
        if (row >= NT) break;
        float4 o;
        o.x = tanhf(acc[i][0] + bv[0]);
        o.y = tanhf(acc[i][1] + bv[1]);
        o.z = tanhf(acc[i][2] + bv[2]);
        o.w = tanhf(acc[i][3] + bv[3]);
        *reinterpret_cast<float4*>(g_h + (size_t)row * DD + col0 + (tx << 2)) = o;
        float ss = o.x * o.x + o.y * o.y + o.z * o.z + o.w * o.w;
        atomicAdd(&g_norm[row], ss);
    }
}

// ---------------- K3: out = h/max(||h||,1e-12) + tanh(pair @ M_sel) ---------
__global__ __launch_bounds__(TPB) void k_out(const float* __restrict__ Mu,
                                             const float* __restrict__ Mi,
                                             float* __restrict__ Out) {
    __shared__ float As[BK][BM + 4];
    __shared__ float Bs[BK][BN];
    const int row0 = blockIdx.x * BM;
    const int col0 = blockIdx.y * BN;
    const float* M = (row0 < NU) ? Mu : Mi;
    float acc[4][4] = {};
    gemm_accum(acc, As, Bs, g_pair, g_pair, NT, M, row0, col0);

    const int tx = threadIdx.x & 15, ty = threadIdx.x >> 4;
#pragma unroll
    for (int i = 0; i < 4; i++) {
        int row = row0 + (ty << 2) + i;
        if (row >= NT) break;
        float nrm = sqrtf(g_norm[row]);
        float s = 1.f / fmaxf(nrm, 1e-12f);
        float4 h = *reinterpret_cast<const float4*>(g_h + (size_t)row * DD + col0 + (tx << 2));
        float4 o;
        o.x = h.x * s + tanhf(acc[i][0]);
        o.y = h.y * s + tanhf(acc[i][1]);
        o.z = h.z * s + tanhf(acc[i][2]);
        o.w = h.w * s + tanhf(acc[i][3]);
        *reinterpret_cast<float4*>(Out + (size_t)row * DD + col0 + (tx << 2)) = o;
    }
}

// ---------------- host-side CSR build + SpMM sequence -----------------------
static inline void build_and_spmm(const int* rows, const int* cols, const float* vals,
                                  int nnz, int n_rows,
                                  const float* X1, const float* X2, int colsplit,
                                  float* Y)
{
    k_zero_cnt<<<(n_rows + 255) / 256, 256>>>(n_rows);
    k_hist<<<(nnz + 255) / 256, 256>>>(rows, nnz);
    k_scan<<<1, 1024>>>(n_rows);
    k_copy_cur<<<(n_rows + 255) / 256, 256>>>(n_rows);
    k_scatter<<<(nnz + 255) / 256, 256>>>(rows, cols, vals, nnz);
    k_spmm_csr<<<(n_rows + 7) / 8, 256>>>(X1, X2, colsplit, Y, n_rows);
}

extern "C" void kernel_launch(void* const* d_in, const int* in_sizes, int n_in,
                              void* d_out, int out_size) {
    const int*   adj_rows = (const int*)d_in[0];
    const int*   adj_cols = (const int*)d_in[1];
    const float* adj_vals = (const float*)d_in[2];
    const int*   up_rows  = (const int*)d_in[3];
    const int*   up_cols  = (const int*)d_in[4];
    const float* up_vals  = (const float*)d_in[5];
    const int*   ip_rows  = (const int*)d_in[6];
    const int*   ip_cols  = (const int*)d_in[7];
    const float* ip_vals  = (const float*)d_in[8];
    const float* Ue       = (const float*)d_in[9];
    const float* Ie       = (const float*)d_in[10];
    const float* Qu       = (const float*)d_in[11];
    const float* Wu       = (const float*)d_in[12];
    const float* bu       = (const float*)d_in[13];
    const float* Qi       = (const float*)d_in[14];
    const float* Wi       = (const float*)d_in[15];
    const float* bi       = (const float*)d_in[16];
    const float* Mu       = (const float*)d_in[17];
    const float* Mi       = (const float*)d_in[18];
    float* out = (float*)d_out;

    float* d_agg;  cudaGetSymbolAddress((void**)&d_agg,  g_agg);
    float* d_pair; cudaGetSymbolAddress((void**)&d_pair, g_pair);

    k_zero_norm<<<(NT + 255) / 256, 256>>>();

    // adj: pre0 = [Ue; Ie], 60000 rows
    build_and_spmm(adj_rows, adj_cols, adj_vals, NNZ_ADJ, NT, Ue, Ie, NU, d_agg);
    // user pairs -> g_pair[0:NU)
    build_and_spmm(up_rows, up_cols, up_vals, NNZ_UP, NU, Ue, Ue, 1 << 30, d_pair);
    // item pairs -> g_pair[NU:NT)
    build_and_spmm(ip_rows, ip_cols, ip_vals, NNZ_IP, NI, Ie, Ie, 1 << 30,
                   d_pair + (size_t)NU * DD);

    dim3 grid((NT + BM - 1) / BM, DD / BN);
    k_emb<<<grid, TPB>>>(Qu, Qi);
    k_hidden<<<grid, TPB>>>(Ue, Ie, Wu, Wi, bu, bi);
    k_out<<<grid, TPB>>>(Mu, Mi, out);
}

// round 4
// speedup vs baseline: 4.4787x; 1.6584x over previous
#include <cuda_runtime.h>
#include <cuda_bf16.h>
#include <math.h>
#include <stdint.h>

#define NU 40000
#define NI 20000
#define NT 60000
#define DD 256
#define NNZ_ADJ 960000
#define NNZ_UP  640000
#define NNZ_IP  320000
#define NNZ_ALL (NNZ_ADJ + NNZ_UP + NNZ_IP)
#define NROWS_ALL (NT + NU + NI)            /* 120000 */
#define SCAN_NB ((NROWS_ALL + 1023) / 1024) /* 118 */

#define NRB_U ((NU + 127) / 128)  /* 313 */
#define NRB_I ((NI + 127) / 128)  /* 157 */
#define NRB (NRB_U + NRB_I)       /* 470 */

typedef __nv_bfloat16 bf16;

// ======================= device scratch =====================================
__device__ bf16 g_pre0h[(size_t)NT * DD], g_pre0l[(size_t)NT * DD];
__device__ bf16 g_aggh[(size_t)NT * DD],  g_aggl[(size_t)NT * DD];
__device__ bf16 g_pairh[(size_t)NT * DD], g_pairl[(size_t)NT * DD];
__device__ bf16 g_embh[(size_t)NT * DD],  g_embl[(size_t)NT * DD];
__device__ float g_h[(size_t)NT * DD];
__device__ float g_norm[NT];
// transposed + split weights ([0]=user, [1]=item)
__device__ bf16 g_Qth[2][DD * DD],     g_Qtl[2][DD * DD];
__device__ bf16 g_Wth[2][DD * 2 * DD], g_Wtl[2][DD * 2 * DD];
__device__ bf16 g_Mth[2][DD * DD],     g_Mtl[2][DD * DD];
// CSR build
__device__ int   g_cnt[NROWS_ALL];
__device__ int   g_rs[NROWS_ALL + 1];
__device__ int   g_cur[NROWS_ALL];
__device__ int   g_ccol[NNZ_ALL];
__device__ float g_cval[NNZ_ALL];
__device__ int   g_bsum[SCAN_NB], g_boff[SCAN_NB + 1];

__device__ __forceinline__ void bsplit(float x, bf16& h, bf16& l) {
    h = __float2bfloat16_rn(x);
    l = __float2bfloat16_rn(x - __bfloat162float(h));
}

// ======================= CSR build ==========================================
__global__ void k_zero_cnt() {
    int i = blockIdx.x * blockDim.x + threadIdx.x;
    if (i < NROWS_ALL) g_cnt[i] = 0;
    if (i < NT) g_norm[i] = 0.f;
}
__global__ void k_hist(const int* __restrict__ rows, int nnz, int off) {
    int i = blockIdx.x * blockDim.x + threadIdx.x;
    if (i < nnz) atomicAdd(&g_cnt[rows[i] + off], 1);
}
__global__ __launch_bounds__(1024) void k_scan_blk() {
    __shared__ int s[1024];
    int i = blockIdx.x * 1024 + threadIdx.x;
    int v = (i < NROWS_ALL) ? g_cnt[i] : 0;
    s[threadIdx.x] = v;
    __syncthreads();
    int x = v;
    for (int off = 1; off < 1024; off <<= 1) {
        int t = (threadIdx.x >= off) ? s[threadIdx.x - off] : 0;
        __syncthreads();
        x += t;
        s[threadIdx.x] = x;
        __syncthreads();
    }
    if (i < NROWS_ALL) g_rs[i] = x - v;  // exclusive (block-local)
    if (threadIdx.x == 1023) g_bsum[blockIdx.x] = s[1023];
}
__global__ void k_scan_top() {
    if (threadIdx.x == 0) {
        int run = 0;
        for (int b = 0; b < SCAN_NB; b++) { g_boff[b] = run; run += g_bsum[b]; }
        g_boff[SCAN_NB] = run;
    }
}
__global__ void k_scan_add() {
    int i = blockIdx.x * 1024 + threadIdx.x;
    if (i < NROWS_ALL) {
        int r = g_rs[i] + g_boff[i >> 10];
        g_rs[i] = r;
        g_cur[i] = r;
    }
    if (i == 0) g_rs[NROWS_ALL] = g_boff[SCAN_NB];
}
__global__ void k_scatter(const int* __restrict__ rows, const int* __restrict__ cols,
                          const float* __restrict__ vals, int nnz, int off) {
    int i = blockIdx.x * blockDim.x + threadIdx.x;
    if (i >= nnz) return;
    int p = atomicAdd(&g_cur[rows[i] + off], 1);
    g_ccol[p] = cols[i];
    g_cval[p] = vals[i];
}

// ======================= unified CSR SpMM (warp/row, bf16-split output) =====
__global__ __launch_bounds__(256) void k_spmm(const float* __restrict__ Ue,
                                              const float* __restrict__ Ie) {
    int R = blockIdx.x * 8 + (threadIdx.x >> 5);
    if (R >= NROWS_ALL) return;
    int lane = threadIdx.x & 31;
    const float* X1;
    const float* X2;
    int split;
    bf16 *oh, *ol;
    int orow;
    if (R < NT)            { X1 = Ue; X2 = Ie; split = NU;      oh = g_aggh;  ol = g_aggl;  orow = R; }
    else if (R < NT + NU)  { X1 = Ue; X2 = Ue; split = 1 << 30; oh = g_pairh; ol = g_pairl; orow = R - NT; }
    else                   { X1 = Ie; X2 = Ie; split = 1 << 30; oh = g_pairh; ol = g_pairl; orow = R - NT; }

    float4 a0 = make_float4(0.f, 0.f, 0.f, 0.f);
    float4 a1 = a0;
    int beg = g_rs[R], end = g_rs[R + 1];
    for (int e = beg; e < end; e++) {
        int c = g_ccol[e];
        float v = g_cval[e];
        const float* x = (c < split) ? (X1 + (size_t)c * DD) : (X2 + (size_t)(c - split) * DD);
        float4 b0 = *reinterpret_cast<const float4*>(x + lane * 4);
        float4 b1 = *reinterpret_cast<const float4*>(x + 128 + lane * 4);
        a0.x += v * b0.x; a0.y += v * b0.y; a0.z += v * b0.z; a0.w += v * b0.w;
        a1.x += v * b1.x; a1.y += v * b1.y; a1.z += v * b1.z; a1.w += v * b1.w;
    }
    size_t base = (size_t)orow * DD + lane * 4;
    bf16 h0, l0, h1, l1, h2, l2, h3, l3;
    bsplit(a0.x, h0, l0); bsplit(a0.y, h1, l1); bsplit(a0.z, h2, l2); bsplit(a0.w, h3, l3);
    oh[base + 0] = h0; oh[base + 1] = h1; oh[base + 2] = h2; oh[base + 3] = h3;
    ol[base + 0] = l0; ol[base + 1] = l1; ol[base + 2] = l2; ol[base + 3] = l3;
    bsplit(a1.x, h0, l0); bsplit(a1.y, h1, l1); bsplit(a1.z, h2, l2); bsplit(a1.w, h3, l3);
    oh[base + 128] = h0; oh[base + 129] = h1; oh[base + 130] = h2; oh[base + 131] = h3;
    ol[base + 128] = l0; ol[base + 129] = l1; ol[base + 130] = l2; ol[base + 131] = l3;
}

// ======================= conversions =========================================
__global__ void k_conv_pre0(const float* __restrict__ Ue, const float* __restrict__ Ie) {
    size_t i = (size_t)blockIdx.x * blockDim.x + threadIdx.x;  // float4 index
    if (i >= (size_t)NT * DD / 4) return;
    size_t base = i * 4;
    const float* src = (base < (size_t)NU * DD) ? (Ue + base) : (Ie + base - (size_t)NU * DD);
    float4 v = *reinterpret_cast<const float4*>(src);
    bf16 h, l;
    bsplit(v.x, h, l); g_pre0h[base + 0] = h; g_pre0l[base + 0] = l;
    bsplit(v.y, h, l); g_pre0h[base + 1] = h; g_pre0l[base + 1] = l;
    bsplit(v.z, h, l); g_pre0h[base + 2] = h; g_pre0l[base + 2] = l;
    bsplit(v.w, h, l); g_pre0h[base + 3] = h; g_pre0l[base + 3] = l;
}

// transpose + split: W[K x 256] -> Th/Tl[256 x K]
__global__ void k_tsplit(const float* __restrict__ W, int K, bf16* __restrict__ Th,
                         bf16* __restrict__ Tl) {
    int i = blockIdx.x * blockDim.x + threadIdx.x;
    if (i >= K * DD) return;
    int k = i >> 8, n = i & 255;
    bf16 h, l;
    bsplit(W[i], h, l);
    Th[(size_t)n * K + k] = h;
    Tl[(size_t)n * K + k] = l;
}

// ======================= legacy-HMMA bf16 GEMM ==============================
// mma.sync.aligned.m16n8k16.row.col.f32.bf16.bf16.f32
__device__ __forceinline__ void mma_bf16(float c[4], const uint32_t a[4],
                                         uint32_t b0, uint32_t b1) {
    asm volatile(
        "mma.sync.aligned.m16n8k16.row.col.f32.bf16.bf16.f32 "
        "{%0,%1,%2,%3}, {%4,%5,%6,%7}, {%8,%9}, {%0,%1,%2,%3};"
        : "+f"(c[0]), "+f"(c[1]), "+f"(c[2]), "+f"(c[3])
        : "r"(a[0]), "r"(a[1]), "r"(a[2]), "r"(a[3]), "r"(b0), "r"(b1));
}

#define SPAD 36  /* smem row stride in bf16 (72B: 8B-aligned, <=2-way conflicts) */

__device__ __forceinline__ void st_tile(bf16* s, int r, int kq, uint4 v) {
    uint2* q = reinterpret_cast<uint2*>(s + r * SPAD + kq * 8);
    q[0] = make_uint2(v.x, v.y);
    q[1] = make_uint2(v.z, v.w);
}
__device__ __forceinline__ uint32_t ld32s(const bf16* s, int elem) {
    return *reinterpret_cast<const uint32_t*>(s + elem);
}

// CTA: 128(m) x 128(n), 8 warps (4 m x 2 n), warp tile 32x64, K-chunks of 32.
// modes: 0 emb=tanh(A@B)->Oh/Ol ; 1 h=tanh(A@B+bias)->Og,+g_norm ;
//        2 out=Hin*rsnorm+tanh(A@B)->Og
__global__ __launch_bounds__(256, 2) void k_gemm(
    int mode, int nch, int nsplit,
    const bf16* __restrict__ A1h, const bf16* __restrict__ A1l,
    const bf16* __restrict__ A2h, const bf16* __restrict__ A2l,
    const bf16* __restrict__ Bth_u, const bf16* __restrict__ Btl_u,
    const bf16* __restrict__ Bth_i, const bf16* __restrict__ Btl_i, int ldb,
    const float* __restrict__ bias_u, const float* __restrict__ bias_i,
    bf16* __restrict__ Oh, bf16* __restrict__ Ol,
    float* __restrict__ Og, const float* __restrict__ Hin)
{
    __shared__ bf16 As_h[128 * SPAD], As_l[128 * SPAD];
    __shared__ bf16 Bs_h[128 * SPAD], Bs_l[128 * SPAD];

    const int tid = threadIdx.x;
    const int wid = tid >> 5, lane = tid & 31;
    const int wm = wid & 3, wn = wid >> 2;
    const int g = lane >> 2, tg = lane & 3;
    const int b = blockIdx.x;
    const bool user = (b < NRB_U);
    const int row0 = user ? b * 128 : NU + (b - NRB_U) * 128;
    const int row_end = user ? NU : NT;
    const int valid = min(128, row_end - row0);
    const int n0 = blockIdx.y * 128;
    const bf16* __restrict__ Bh = user ? Bth_u : Bth_i;
    const bf16* __restrict__ Bl = user ? Btl_u : Btl_i;
    const float* __restrict__ bias = user ? bias_u : bias_i;

    float acc[2][8][4];
#pragma unroll
    for (int mi = 0; mi < 2; mi++)
#pragma unroll
        for (int ni = 0; ni < 8; ni++)
#pragma unroll
            for (int j = 0; j < 4; j++) acc[mi][ni][j] = 0.f;

    for (int ch = 0; ch < nch; ch++) {
        const bf16* Ah = (ch < nsplit) ? A1h : A2h;
        const bf16* Al = (ch < nsplit) ? A1l : A2l;
        const int ka = ((ch < nsplit) ? ch : ch - nsplit) * 32;
        const int kb = ch * 32;
        if (ch) __syncthreads();
#pragma unroll
        for (int it = 0; it < 2; it++) {
            int idx = it * 256 + tid;      // 0..511
            int r = idx >> 2, kq = idx & 3;
            uint4 vah = make_uint4(0, 0, 0, 0), val_ = vah;
            if (r < valid) {
                size_t off = (size_t)(row0 + r) * DD + ka + kq * 8;
                vah  = *reinterpret_cast<const uint4*>(Ah + off);
                val_ = *reinterpret_cast<const uint4*>(Al + off);
            }
            st_tile(As_h, r, kq, vah);
            st_tile(As_l, r, kq, val_);
            size_t boff = (size_t)(n0 + r) * ldb + kb + kq * 8;
            st_tile(Bs_h, r, kq, *reinterpret_cast<const uint4*>(Bh + boff));
            st_tile(Bs_l, r, kq, *reinterpret_cast<const uint4*>(Bl + boff));
        }
        __syncthreads();

#pragma unroll
        for (int ks = 0; ks < 2; ks++) {
            const int kc = ks * 16 + 2 * tg;
            uint32_t ah[2][4], al[2][4];
#pragma unroll
            for (int mi = 0; mi < 2; mi++) {
                int rb = (wm * 32 + mi * 16 + g) * SPAD;
                ah[mi][0] = ld32s(As_h, rb + kc);
                ah[mi][1] = ld32s(As_h, rb + 8 * SPAD + kc);
                ah[mi][2] = ld32s(As_h, rb + kc + 8);
                ah[mi][3] = ld32s(As_h, rb + 8 * SPAD + kc + 8);
                al[mi][0] = ld32s(As_l, rb + kc);
                al[mi][1] = ld32s(As_l, rb + 8 * SPAD + kc);
                al[mi][2] = ld32s(As_l, rb + kc + 8);
                al[mi][3] = ld32s(As_l, rb + 8 * SPAD + kc + 8);
            }
#pragma unroll
            for (int ni = 0; ni < 8; ni++) {
                int nb = (wn * 64 + ni * 8 + g) * SPAD;
                uint32_t bh0 = ld32s(Bs_h, nb + kc);
                uint32_t bh1 = ld32s(Bs_h, nb + kc + 8);
                uint32_t bl0 = ld32s(Bs_l, nb + kc);
                uint32_t bl1 = ld32s(Bs_l, nb + kc + 8);
#pragma unroll
                for (int mi = 0; mi < 2; mi++) {
                    mma_bf16(acc[mi][ni], ah[mi], bh0, bh1);
                    mma_bf16(acc[mi][ni], ah[mi], bl0, bl1);
                    mma_bf16(acc[mi][ni], al[mi], bh0, bh1);
                }
            }
        }
    }

    // ---------------- epilogue ----------------
    const int mbase = row0 + wm * 32 + g;
    float scl[2][2];
    if (mode == 2) {
#pragma unroll
        for (int mi = 0; mi < 2; mi++) {
            int r0 = mbase + mi * 16, r1 = r0 + 8;
            scl[mi][0] = (r0 < row_end) ? 1.f / fmaxf(sqrtf(g_norm[r0]), 1e-12f) : 0.f;
            scl[mi][1] = (r1 < row_end) ? 1.f / fmaxf(sqrtf(g_norm[r1]), 1e-12f) : 0.f;
        }
    }
    float ssum[4] = {0.f, 0.f, 0.f, 0.f};

#pragma unroll
    for (int mi = 0; mi < 2; mi++) {
        int r0 = mbase + mi * 16, r1 = r0 + 8;
        bool v0 = (r0 < row_end), v1 = (r1 < row_end);
#pragma unroll
        for (int ni = 0; ni < 8; ni++) {
            int col = n0 + wn * 64 + ni * 8 + 2 * tg;
            float* a = acc[mi][ni];
            if (mode == 0) {
                if (v0) {
                    float t0 = tanhf(a[0]), t1 = tanhf(a[1]);
                    bf16 h0, l0, h1, l1;
                    bsplit(t0, h0, l0); bsplit(t1, h1, l1);
                    size_t idx = (size_t)r0 * DD + col;
                    *reinterpret_cast<__nv_bfloat162*>(Oh + idx) = __nv_bfloat162(h0, h1);
                    *reinterpret_cast<__nv_bfloat162*>(Ol + idx) = __nv_bfloat162(l0, l1);
                }
                if (v1) {
                    float t2 = tanhf(a[2]), t3 = tanhf(a[3]);
                    bf16 h2, l2, h3, l3;
                    bsplit(t2, h2, l2); bsplit(t3, h3, l3);
                    size_t idx = (size_t)r1 * DD + col;
                    *reinterpret_cast<__nv_bfloat162*>(Oh + idx) = __nv_bfloat162(h2, h3);
                    *reinterpret_cast<__nv_bfloat162*>(Ol + idx) = __nv_bfloat162(l2, l3);
                }
            } else if (mode == 1) {
                float b0v = bias[col], b1v = bias[col + 1];
                if (v0) {
                    float t0 = tanhf(a[0] + b0v), t1 = tanhf(a[1] + b1v);
                    size_t idx = (size_t)r0 * DD + col;
                    Og[idx] = t0; Og[idx + 1] = t1;
                    ssum[mi * 2] += t0 * t0 + t1 * t1;
                }
                if (v1) {
                    float t2 = tanhf(a[2] + b0v), t3 = tanhf(a[3] + b1v);
                    size_t idx = (size_t)r1 * DD + col;
                    Og[idx] = t2; Og[idx + 1] = t3;
                    ssum[mi * 2 + 1] += t2 * t2 + t3 * t3;
                }
            } else {
                if (v0) {
                    size_t idx = (size_t)r0 * DD + col;
                    Og[idx]     = Hin[idx]     * scl[mi][0] + tanhf(a[0]);
                    Og[idx + 1] = Hin[idx + 1] * scl[mi][0] + tanhf(a[1]);
                }
                if (v1) {
                    size_t idx = (size_t)r1 * DD + col;
                    Og[idx]     = Hin[idx]     * scl[mi][1] + tanhf(a[2]);
                    Og[idx + 1] = Hin[idx + 1] * scl[mi][1] + tanhf(a[3]);
                }
            }
        }
    }
    if (mode == 1) {
#pragma unroll
        for (int j = 0; j < 4; j++) {
            ssum[j] += __shfl_xor_sync(0xFFFFFFFF, ssum[j], 1);
            ssum[j] += __shfl_xor_sync(0xFFFFFFFF, ssum[j], 2);
        }
        if (tg == 0) {
#pragma unroll
            for (int mi = 0; mi < 2; mi++) {
                int r0 = mbase + mi * 16, r1 = r0 + 8;
                if (r0 < row_end) atomicAdd(&g_norm[r0], ssum[mi * 2]);
                if (r1 < row_end) atomicAdd(&g_norm[r1], ssum[mi * 2 + 1]);
            }
        }
    }
}

// ======================= host ================================================
extern "C" void kernel_launch(void* const* d_in, const int* in_sizes, int n_in,
                              void* d_out, int out_size) {
    const int*   adj_rows = (const int*)d_in[0];
    const int*   adj_cols = (const int*)d_in[1];
    const float* adj_vals = (const float*)d_in[2];
    const int*   up_rows  = (const int*)d_in[3];
    const int*   up_cols  = (const int*)d_in[4];
    const float* up_vals  = (const float*)d_in[5];
    const int*   ip_rows  = (const int*)d_in[6];
    const int*   ip_cols  = (const int*)d_in[7];
    const float* ip_vals  = (const float*)d_in[8];
    const float* Ue       = (const float*)d_in[9];
    const float* Ie       = (const float*)d_in[10];
    const float* Qu       = (const float*)d_in[11];
    const float* Wu       = (const float*)d_in[12];
    const float* bu       = (const float*)d_in[13];
    const float* Qi       = (const float*)d_in[14];
    const float* Wi       = (const float*)d_in[15];
    const float* bi       = (const float*)d_in[16];
    const float* Mu       = (const float*)d_in[17];
    const float* Mi       = (const float*)d_in[18];
    float* out = (float*)d_out;

    bf16 *pre0h, *pre0l, *aggh, *aggl, *pairh, *pairl, *embh, *embl;
    bf16 *qth, *qtl, *wth, *wtl, *mth, *mtl;
    float* hbuf;
    cudaGetSymbolAddress((void**)&pre0h, g_pre0h);
    cudaGetSymbolAddress((void**)&pre0l, g_pre0l);
    cudaGetSymbolAddress((void**)&aggh,  g_aggh);
    cudaGetSymbolAddress((void**)&aggl,  g_aggl);
    cudaGetSymbolAddress((void**)&pairh, g_pairh);
    cudaGetSymbolAddress((void**)&pairl, g_pairl);
    cudaGetSymbolAddress((void**)&embh,  g_embh);
    cudaGetSymbolAddress((void**)&embl,  g_embl);
    cudaGetSymbolAddress((void**)&qth,   g_Qth);
    cudaGetSymbolAddress((void**)&qtl,   g_Qtl);
    cudaGetSymbolAddress((void**)&wth,   g_Wth);
    cudaGetSymbolAddress((void**)&wtl,   g_Wtl);
    cudaGetSymbolAddress((void**)&mth,   g_Mth);
    cudaGetSymbolAddress((void**)&mtl,   g_Mtl);
    cudaGetSymbolAddress((void**)&hbuf,  g_h);

    // ---- CSR build (unified row space) + norm zero ----
    k_zero_cnt<<<(NROWS_ALL + 255) / 256, 256>>>();
    k_hist<<<(NNZ_ADJ + 255) / 256, 256>>>(adj_rows, NNZ_ADJ, 0);
    k_hist<<<(NNZ_UP + 255) / 256, 256>>>(up_rows, NNZ_UP, NT);
    k_hist<<<(NNZ_IP + 255) / 256, 256>>>(ip_rows, NNZ_IP, NT + NU);
    k_scan_blk<<<SCAN_NB, 1024>>>();
    k_scan_top<<<1, 32>>>();
    k_scan_add<<<SCAN_NB, 1024>>>();
    k_scatter<<<(NNZ_ADJ + 255) / 256, 256>>>(adj_rows, adj_cols, adj_vals, NNZ_ADJ, 0);
    k_scatter<<<(NNZ_UP + 255) / 256, 256>>>(up_rows, up_cols, up_vals, NNZ_UP, NT);
    k_scatter<<<(NNZ_IP + 255) / 256, 256>>>(ip_rows, ip_cols, ip_vals, NNZ_IP, NT + NU);

    // ---- SpMM (all three), bf16-split outputs ----
    k_spmm<<<(NROWS_ALL + 7) / 8, 256>>>(Ue, Ie);

    // ---- conversions ----
    k_conv_pre0<<<(NT * DD / 4 + 255) / 256, 256>>>(Ue, Ie);
    k_tsplit<<<(DD * DD + 255) / 256, 256>>>(Qu, DD, qth, qtl);
    k_tsplit<<<(DD * DD + 255) / 256, 256>>>(Qi, DD, qth + (size_t)DD * DD, qtl + (size_t)DD * DD);
    k_tsplit<<<(2 * DD * DD + 255) / 256, 256>>>(Wu, 2 * DD, wth, wtl);
    k_tsplit<<<(2 * DD * DD + 255) / 256, 256>>>(Wi, 2 * DD, wth + (size_t)2 * DD * DD, wtl + (size_t)2 * DD * DD);
    k_tsplit<<<(DD * DD + 255) / 256, 256>>>(Mu, DD, mth, mtl);
    k_tsplit<<<(DD * DD + 255) / 256, 256>>>(Mi, DD, mth + (size_t)DD * DD, mtl + (size_t)DD * DD);

    dim3 ggrid(NRB, 2);

    // ---- GEMM 1: emb = tanh(agg @ Q_sel) ----
    k_gemm<<<ggrid, 256>>>(0, 8, 8,
        aggh, aggl, aggh, aggl,
        qth, qtl, qth + (size_t)DD * DD, qtl + (size_t)DD * DD, DD,
        nullptr, nullptr, embh, embl, nullptr, nullptr);

    // ---- GEMM 2: h = tanh([pre0, emb] @ W_sel + b_sel), row norms ----
    k_gemm<<<ggrid, 256>>>(1, 16, 8,
        pre0h, pre0l, embh, embl,
        wth, wtl, wth + (size_t)2 * DD * DD, wtl + (size_t)2 * DD * DD, 2 * DD,
        bu, bi, nullptr, nullptr, hbuf, nullptr);

    // ---- GEMM 3: out = h/||h|| + tanh(pair @ M_sel) ----
    k_gemm<<<ggrid, 256>>>(2, 8, 8,
        pairh, pairl, pairh, pairl,
        mth, mtl, mth + (size_t)DD * DD, mtl + (size_t)DD * DD, DD,
        nullptr, nullptr, nullptr, nullptr, out, hbuf);
}